// round 4
// baseline (speedup 1.0000x reference)
#include <cuda_runtime.h>
#include <cuda_bf16.h>
#include <cstdint>

// Problem shape (fixed by the reference):
//   data:  [B, C, N]  float32
//   edges: [E, 2]     int32
//   out:   [B, C, N+E] float32; first N cols per row are zero,
//          col N+e = (data[bc, p0] + data[bc, p1]) * 0.5
static constexpr int B_  = 4;
static constexpr int C_  = 128;
static constexpr int N_  = 100000;
static constexpr int E_  = 200000;
static constexpr int BC_ = B_ * C_;
static constexpr int M_  = N_ + E_;        // 300000, row length of output
static constexpr int M4_ = M_ / 4;         // 75000 float4 per row
static constexpr int N4_ = N_ / 4;         // 25000 float4 zero head

__global__ __launch_bounds__(256)
void upsample_mid_kernel(const float* __restrict__ data,
                         const int*   __restrict__ edges,
                         float*       __restrict__ out) {
    const int j4 = blockIdx.x * blockDim.x + threadIdx.x;  // float4 col index
    const int bc = blockIdx.y;
    if (j4 >= M4_) return;

    float4* __restrict__ orow =
        reinterpret_cast<float4*>(out + (size_t)bc * M_);

    if (j4 < N4_) {
        // zero head
        orow[j4] = make_float4(0.f, 0.f, 0.f, 0.f);
    } else {
        // four consecutive edges e .. e+3
        const int e = j4 * 4 - N_;                 // multiple of 4
        const int4* __restrict__ ev = reinterpret_cast<const int4*>(edges);
        // edges flat: [e0.p0, e0.p1, e1.p0, e1.p1, ...]; int4 idx = e/2
        const int4 e01 = __ldg(&ev[e >> 1]);       // edges e, e+1
        const int4 e23 = __ldg(&ev[(e >> 1) + 1]); // edges e+2, e+3

        const float* __restrict__ drow = data + (size_t)bc * N_;
        float4 r;
        r.x = (__ldg(drow + e01.x) + __ldg(drow + e01.y)) * 0.5f;
        r.y = (__ldg(drow + e01.z) + __ldg(drow + e01.w)) * 0.5f;
        r.z = (__ldg(drow + e23.x) + __ldg(drow + e23.y)) * 0.5f;
        r.w = (__ldg(drow + e23.z) + __ldg(drow + e23.w)) * 0.5f;
        orow[j4] = r;
    }
}

extern "C" void kernel_launch(void* const* d_in, const int* in_sizes, int n_in,
                              void* d_out, int out_size) {
    const float* data  = (const float*)d_in[0];   // [B, C, N] fp32
    const int*   edges = (const int*)d_in[1];     // [E, 2] int32
    float*       out   = (float*)d_out;           // [B, C, N+E] fp32

    const int threads = 256;
    dim3 grid((M4_ + threads - 1) / threads, BC_);
    upsample_mid_kernel<<<grid, threads>>>(data, edges, out);
}

// round 5
// speedup vs baseline: 1.0008x; 1.0008x over previous
#include <cuda_runtime.h>
#include <cuda_bf16.h>
#include <cstdint>

// Problem shape (fixed by the reference):
//   data:  [B, C, N]  float32
//   edges: [E, 2]     int32
//   out:   [B, C, N+E] float32; first N cols per row are zero,
//          col N+e = (data[bc, p0] + data[bc, p1]) * 0.5
static constexpr int B_  = 4;
static constexpr int C_  = 128;
static constexpr int N_  = 100000;
static constexpr int E_  = 200000;
static constexpr int BC_ = B_ * C_;
static constexpr int M_  = N_ + E_;        // 300000, row length of output
static constexpr int M4_ = M_ / 4;         // 75000 float4 per row
static constexpr int N4_ = N_ / 4;         // 25000 float4 zero head

__global__ __launch_bounds__(256)
void upsample_mid_kernel(const float* __restrict__ data,
                         const int*   __restrict__ edges,
                         float*       __restrict__ out) {
    const int j4 = blockIdx.x * blockDim.x + threadIdx.x;  // float4 col index
    const int bc = blockIdx.y;
    if (j4 >= M4_) return;

    float4* __restrict__ orow =
        reinterpret_cast<float4*>(out + (size_t)bc * M_);

    if (j4 < N4_) {
        // zero head
        orow[j4] = make_float4(0.f, 0.f, 0.f, 0.f);
    } else {
        // four consecutive edges e .. e+3
        const int e = j4 * 4 - N_;                 // multiple of 4
        const int4* __restrict__ ev = reinterpret_cast<const int4*>(edges);
        // edges flat: [e0.p0, e0.p1, e1.p0, e1.p1, ...]; int4 idx = e/2
        const int4 e01 = __ldg(&ev[e >> 1]);       // edges e, e+1
        const int4 e23 = __ldg(&ev[(e >> 1) + 1]); // edges e+2, e+3

        const float* __restrict__ drow = data + (size_t)bc * N_;
        float4 r;
        r.x = (__ldg(drow + e01.x) + __ldg(drow + e01.y)) * 0.5f;
        r.y = (__ldg(drow + e01.z) + __ldg(drow + e01.w)) * 0.5f;
        r.z = (__ldg(drow + e23.x) + __ldg(drow + e23.y)) * 0.5f;
        r.w = (__ldg(drow + e23.z) + __ldg(drow + e23.w)) * 0.5f;
        orow[j4] = r;
    }
}

extern "C" void kernel_launch(void* const* d_in, const int* in_sizes, int n_in,
                              void* d_out, int out_size) {
    const float* data  = (const float*)d_in[0];   // [B, C, N] fp32
    const int*   edges = (const int*)d_in[1];     // [E, 2] int32
    float*       out   = (float*)d_out;           // [B, C, N+E] fp32

    const int threads = 256;
    dim3 grid((M4_ + threads - 1) / threads, BC_);
    upsample_mid_kernel<<<grid, threads>>>(data, edges, out);
}

// round 6
// speedup vs baseline: 1.6952x; 1.6939x over previous
#include <cuda_runtime.h>
#include <cuda_bf16.h>
#include <cstdint>

// data:  [B, C, N] fp32;  edges: [E, 2] int32
// out:   [B, C, N+E] fp32; head N cols zero, col N+e = (d[p0]+d[p1])*0.5
static constexpr int B_   = 4;
static constexpr int C_   = 128;
static constexpr int N_   = 100000;     // = 32 * 3125
static constexpr int E_   = 200000;
static constexpr int BC_  = B_ * C_;    // 512
static constexpr int M_   = N_ + E_;    // 300000
static constexpr int N4_  = N_ / 4;     // 25000

// Scratch: transposed data [N][BC] (205 MB, __device__ global => allowed)
__device__ float g_dataT[(size_t)N_ * BC_];

// ---------------------------------------------------------------------------
// Kernel 1: transpose data [BC, N] -> dataT [N, BC]. Classic 32x32 SMEM tile.
// grid (N/32 = 3125, BC/32 = 16), block (32, 8)
// ---------------------------------------------------------------------------
__global__ __launch_bounds__(256)
void transpose_kernel(const float* __restrict__ data) {
    __shared__ float tile[32][33];
    const int n0  = blockIdx.x * 32;
    const int bc0 = blockIdx.y * 32;
    const int tx = threadIdx.x, ty = threadIdx.y;

    #pragma unroll
    for (int k = 0; k < 32; k += 8) {
        // read data[bc0+ty+k][n0+tx] (coalesced along n)
        tile[ty + k][tx] = __ldg(&data[(size_t)(bc0 + ty + k) * N_ + n0 + tx]);
    }
    __syncthreads();
    #pragma unroll
    for (int k = 0; k < 32; k += 8) {
        // write dataT[n0+ty+k][bc0+tx] (coalesced along bc)
        g_dataT[(size_t)(n0 + ty + k) * BC_ + bc0 + tx] = tile[tx][ty + k];
    }
}

// ---------------------------------------------------------------------------
// Kernel 2: zero head. out[bc][0..N) = 0 as float4.
// grid (N4/250 = 100, BC), block 250? keep 256 w/ guard.
// ---------------------------------------------------------------------------
__global__ __launch_bounds__(256)
void zero_head_kernel(float* __restrict__ out) {
    const int j4 = blockIdx.x * blockDim.x + threadIdx.x;
    if (j4 >= N4_) return;
    float4* orow = reinterpret_cast<float4*>(out + (size_t)blockIdx.y * M_);
    orow[j4] = make_float4(0.f, 0.f, 0.f, 0.f);
}

// ---------------------------------------------------------------------------
// Kernel 3: gather in transposed space + SMEM transpose-on-write.
// CTA = 32 edges. 512 threads.
//   Phase A: for each local edge el, thread t reads dataT[p0][t], dataT[p1][t]
//            (coalesced 2KB rows), avg -> smem mid[el][t]   (pad 513: no conflicts)
//   Phase B: warp w, lane l: bc = iter*64 + w*4 + l/8, j = l%8
//            writes out[bc][N + e0 + 4j .. +3] as float4 (128B contiguous per 8 lanes)
// ---------------------------------------------------------------------------
static constexpr int TILE_E = 32;

__global__ __launch_bounds__(512)
void gather_mid_kernel(const int* __restrict__ edges,
                       float*     __restrict__ out) {
    __shared__ float  mid[TILE_E][BC_ + 1];   // [32][513] = 65.7 KB
    __shared__ int    sedge[TILE_E * 2];

    const int t  = threadIdx.x;
    const int e0 = blockIdx.x * TILE_E;

    if (t < TILE_E * 2) sedge[t] = __ldg(&edges[e0 * 2 + t]);
    __syncthreads();

    // Phase A: gather + average (coalesced reads of dataT rows)
    #pragma unroll 4
    for (int el = 0; el < TILE_E; ++el) {
        const int p0 = sedge[2 * el];
        const int p1 = sedge[2 * el + 1];
        const float a = __ldg(&g_dataT[(size_t)p0 * BC_ + t]);
        const float b = __ldg(&g_dataT[(size_t)p1 * BC_ + t]);
        mid[el][t] = (a + b) * 0.5f;
    }
    __syncthreads();

    // Phase B: transpose-on-write
    const int w = t >> 5;          // warp 0..15
    const int l = t & 31;
    const int j = l & 7;           // float4 index within edge tile
    #pragma unroll
    for (int iter = 0; iter < BC_ / 64; ++iter) {   // 8 iters
        const int bc = iter * 64 + w * 4 + (l >> 3);
        float4 r;
        r.x = mid[4 * j + 0][bc];
        r.y = mid[4 * j + 1][bc];
        r.z = mid[4 * j + 2][bc];
        r.w = mid[4 * j + 3][bc];
        float4* dst = reinterpret_cast<float4*>(out + (size_t)bc * M_ + N_ + e0);
        dst[j] = r;
    }
}

extern "C" void kernel_launch(void* const* d_in, const int* in_sizes, int n_in,
                              void* d_out, int out_size) {
    const float* data  = (const float*)d_in[0];
    const int*   edges = (const int*)d_in[1];
    float*       out   = (float*)d_out;

    // 1) transpose data -> g_dataT
    dim3 tgrid(N_ / 32, BC_ / 32);
    transpose_kernel<<<tgrid, dim3(32, 8)>>>(data);

    // 2) zero head
    dim3 zgrid((N4_ + 255) / 256, BC_);
    zero_head_kernel<<<zgrid, 256>>>(out);

    // 3) gather + write mids
    gather_mid_kernel<<<E_ / TILE_E, 512>>>(edges, out);
}

// round 7
// speedup vs baseline: 2.6475x; 1.5617x over previous
#include <cuda_runtime.h>
#include <cuda_bf16.h>
#include <cstdint>

// data:  [B, C, N] fp32;  edges: [E, 2] int32
// out:   [B, C, N+E] fp32; head N cols zero, col N+e = (d[p0]+d[p1])*0.5
static constexpr int B_   = 4;
static constexpr int C_   = 128;
static constexpr int N_   = 100000;     // 32 * 3125
static constexpr int E_   = 200000;
static constexpr int BC_  = B_ * C_;    // 512
static constexpr int M_   = N_ + E_;    // 300000
static constexpr int N4_  = N_ / 4;     // 25000
static constexpr int M4_  = M_ / 4;     // 75000
static constexpr int BC4_ = BC_ / 4;    // 128

// Scratch: transposed data [N][BC] fp32 (205 MB)
__device__ float g_dataT[(size_t)N_ * BC_];

// ---------------------------------------------------------------------------
// Kernel 1: transpose data [BC, N] -> dataT [N, BC].
// Tile: 128 bc x 32 n.  grid (N/32 = 3125, BC/128 = 4), block 256.
// Reads: 128B coalesced per row. Writes: float4 over bc, 512B per n row.
// ---------------------------------------------------------------------------
__global__ __launch_bounds__(256)
void transpose_kernel(const float* __restrict__ data) {
    __shared__ float tile[128][33];          // stride 33: conflict-free both phases
    const int n0  = blockIdx.x * 32;
    const int bc0 = blockIdx.y * 128;
    const int tx  = threadIdx.x & 31;
    const int r0  = threadIdx.x >> 5;        // 0..7

    #pragma unroll
    for (int k = 0; k < 16; ++k) {
        const int row = k * 8 + r0;          // 0..127 (bc within tile)
        tile[row][tx] = __ldg(&data[(size_t)(bc0 + row) * N_ + n0 + tx]);
    }
    __syncthreads();

    const int w  = threadIdx.x >> 5;         // 0..7
    const int l  = threadIdx.x & 31;
    const int nl = w * 4 + (l >> 3);         // n within tile, 0..31
    const int c8 = l & 7;
    float4* __restrict__ dT4 = reinterpret_cast<float4*>(g_dataT);
    #pragma unroll
    for (int i = 0; i < 4; ++i) {
        const int c4 = c8 + 8 * i;           // bc float4 within tile, 0..31
        float4 v;
        v.x = tile[4 * c4 + 0][nl];
        v.y = tile[4 * c4 + 1][nl];
        v.z = tile[4 * c4 + 2][nl];
        v.w = tile[4 * c4 + 3][nl];
        dT4[(size_t)(n0 + nl) * BC4_ + (bc0 >> 2) + c4] = v;
    }
}

// ---------------------------------------------------------------------------
// Kernel 2: fused zero-head + gather. CTA = 32 edges, 512 threads.
// SMEM mid: logical [32 edges][512 bc] floats, XOR-swizzled so that
//   phase A float4 stores  (word = el*512 + 4*(m ^ (el>>2)) + k)  and
//   phase B scalar column reads are both bank-conflict-free. 64 KB exactly.
// ---------------------------------------------------------------------------
static constexpr int TILE_E = 32;

__global__ __launch_bounds__(512)
void gather_mid_kernel(const int* __restrict__ edges,
                       float*     __restrict__ out) {
    __shared__ float mid[TILE_E * BC_];      // 64 KB, swizzled
    __shared__ int   sedge[TILE_E * 2];

    const int t  = threadIdx.x;
    const int e0 = blockIdx.x * TILE_E;

    // ---- fused zero head: grid covers exactly BC_*N4_ = 12.8M float4 ----
    {
        const float4 z = make_float4(0.f, 0.f, 0.f, 0.f);
        float4* __restrict__ o4 = reinterpret_cast<float4*>(out);
        #pragma unroll
        for (int k = 0; k < 4; ++k) {
            const int idx = blockIdx.x * 2048 + k * 512 + t;
            const int bc  = idx / N4_;
            const int j4  = idx - bc * N4_;
            o4[(size_t)bc * M4_ + j4] = z;
        }
    }

    if (t < TILE_E * 2) sedge[t] = __ldg(&edges[e0 * 2 + t]);
    __syncthreads();

    // ---- phase A: float4 gather-average in transposed space ----
    const int q = t >> 7;                    // edge slot 0..3 (4 edges in parallel)
    const int m = t & 127;                   // bc float4 index 0..127
    const float4* __restrict__ dT4 = reinterpret_cast<const float4*>(g_dataT);
    float4* __restrict__ mid4 = reinterpret_cast<float4*>(mid);

    #pragma unroll 2
    for (int it = 0; it < 8; ++it) {
        const int el = it * 4 + q;
        const int p0 = sedge[2 * el];
        const int p1 = sedge[2 * el + 1];
        const float4 a = __ldg(&dT4[(size_t)p0 * BC4_ + m]);
        const float4 b = __ldg(&dT4[(size_t)p1 * BC4_ + m]);
        float4 r;
        r.x = (a.x + b.x) * 0.5f;
        r.y = (a.y + b.y) * 0.5f;
        r.z = (a.z + b.z) * 0.5f;
        r.w = (a.w + b.w) * 0.5f;
        mid4[el * BC4_ + (m ^ (el >> 2))] = r;   // swizzled, conflict-free
    }
    __syncthreads();

    // ---- phase B: transpose-on-write, 128B coalesced float4 stores ----
    const int w = t >> 5;                    // warp 0..15
    const int l = t & 31;
    const int j = l & 7;                     // float4 index within 32-edge span
    #pragma unroll
    for (int iter = 0; iter < BC_ / 64; ++iter) {
        const int bc = iter * 64 + w * 4 + (l >> 3);
        const int c4 = bc >> 2;
        const int b3 = bc & 3;
        float4 r;
        r.x = mid[(4 * j + 0) * BC_ + 4 * (c4 ^ j) + b3];
        r.y = mid[(4 * j + 1) * BC_ + 4 * (c4 ^ j) + b3];
        r.z = mid[(4 * j + 2) * BC_ + 4 * (c4 ^ j) + b3];
        r.w = mid[(4 * j + 3) * BC_ + 4 * (c4 ^ j) + b3];
        float4* __restrict__ dst =
            reinterpret_cast<float4*>(out + (size_t)bc * M_);
        dst[N4_ + (e0 >> 2) + j] = r;
    }
}

extern "C" void kernel_launch(void* const* d_in, const int* in_sizes, int n_in,
                              void* d_out, int out_size) {
    const float* data  = (const float*)d_in[0];
    const int*   edges = (const int*)d_in[1];
    float*       out   = (float*)d_out;

    transpose_kernel<<<dim3(N_ / 32, BC_ / 128), 256>>>(data);
    gather_mid_kernel<<<E_ / TILE_E, 512>>>(edges, out);
}

// round 8
// speedup vs baseline: 2.6625x; 1.0057x over previous
#include <cuda_runtime.h>
#include <cuda_bf16.h>
#include <cstdint>

// data:  [B, C, N] fp32;  edges: [E, 2] int32
// out:   [B, C, N+E] fp32; head N cols zero, col N+e = (d[p0]+d[p1])*0.5
static constexpr int B_   = 4;
static constexpr int C_   = 128;
static constexpr int N_   = 100000;     // 32 * 3125
static constexpr int E_   = 200000;
static constexpr int BC_  = B_ * C_;    // 512
static constexpr int M_   = N_ + E_;    // 300000
static constexpr int N4_  = N_ / 4;     // 25000
static constexpr int M4_  = M_ / 4;     // 75000
static constexpr int BC4_ = BC_ / 4;    // 128

// Scratch: transposed data [N][BC] fp32 (205 MB)
__device__ float g_dataT[(size_t)N_ * BC_];

// ---------------------------------------------------------------------------
// Kernel 1: transpose data [BC, N] -> dataT [N, BC].  (measured at BW roofline)
// ---------------------------------------------------------------------------
__global__ __launch_bounds__(256)
void transpose_kernel(const float* __restrict__ data) {
    __shared__ float tile[128][33];
    const int n0  = blockIdx.x * 32;
    const int bc0 = blockIdx.y * 128;
    const int tx  = threadIdx.x & 31;
    const int r0  = threadIdx.x >> 5;

    #pragma unroll
    for (int k = 0; k < 16; ++k) {
        const int row = k * 8 + r0;
        tile[row][tx] = __ldg(&data[(size_t)(bc0 + row) * N_ + n0 + tx]);
    }
    __syncthreads();

    const int w  = threadIdx.x >> 5;
    const int l  = threadIdx.x & 31;
    const int nl = w * 4 + (l >> 3);
    const int c8 = l & 7;
    float4* __restrict__ dT4 = reinterpret_cast<float4*>(g_dataT);
    #pragma unroll
    for (int i = 0; i < 4; ++i) {
        const int c4 = c8 + 8 * i;
        float4 v;
        v.x = tile[4 * c4 + 0][nl];
        v.y = tile[4 * c4 + 1][nl];
        v.z = tile[4 * c4 + 2][nl];
        v.w = tile[4 * c4 + 3][nl];
        // default caching: gather kernel re-reads dataT, keep it in L2
        dT4[(size_t)(n0 + nl) * BC4_ + (bc0 >> 2) + c4] = v;
    }
}

// ---------------------------------------------------------------------------
// Kernel 2: fused zero-head + gather. CTA = 32 edges, 512 threads.
// All output stores use __stcs (streaming) so the 615 MB write stream does
// not evict dataT from L2 (dataT reuse ~4x is the only L2-exploitable reuse).
// ---------------------------------------------------------------------------
static constexpr int TILE_E = 32;

__global__ __launch_bounds__(512)
void gather_mid_kernel(const int* __restrict__ edges,
                       float*     __restrict__ out) {
    __shared__ float mid[TILE_E * BC_];      // 64 KB, XOR-swizzled
    __shared__ int   sedge[TILE_E * 2];

    const int t  = threadIdx.x;
    const int e0 = blockIdx.x * TILE_E;

    // ---- fused zero head (streaming stores) ----
    {
        const float4 z = make_float4(0.f, 0.f, 0.f, 0.f);
        float4* __restrict__ o4 = reinterpret_cast<float4*>(out);
        #pragma unroll
        for (int k = 0; k < 4; ++k) {
            const int idx = blockIdx.x * 2048 + k * 512 + t;
            const int bc  = idx / N4_;
            const int j4  = idx - bc * N4_;
            __stcs(&o4[(size_t)bc * M4_ + j4], z);
        }
    }

    if (t < TILE_E * 2) sedge[t] = __ldg(&edges[e0 * 2 + t]);
    __syncthreads();

    // ---- phase A: float4 gather-average in transposed space ----
    const int q = t >> 7;                    // edge slot 0..3
    const int m = t & 127;                   // bc float4 index
    const float4* __restrict__ dT4 = reinterpret_cast<const float4*>(g_dataT);
    float4* __restrict__ mid4 = reinterpret_cast<float4*>(mid);

    #pragma unroll 4
    for (int it = 0; it < 8; ++it) {
        const int el = it * 4 + q;
        const int p0 = sedge[2 * el];
        const int p1 = sedge[2 * el + 1];
        const float4 a = __ldg(&dT4[(size_t)p0 * BC4_ + m]);
        const float4 b = __ldg(&dT4[(size_t)p1 * BC4_ + m]);
        float4 r;
        r.x = (a.x + b.x) * 0.5f;
        r.y = (a.y + b.y) * 0.5f;
        r.z = (a.z + b.z) * 0.5f;
        r.w = (a.w + b.w) * 0.5f;
        mid4[el * BC4_ + (m ^ (el >> 2))] = r;   // conflict-free swizzle
    }
    __syncthreads();

    // ---- phase B: transpose-on-write, 128B coalesced streaming stores ----
    const int w = t >> 5;
    const int l = t & 31;
    const int j = l & 7;
    #pragma unroll
    for (int iter = 0; iter < BC_ / 64; ++iter) {
        const int bc = iter * 64 + w * 4 + (l >> 3);
        const int c4 = bc >> 2;
        const int b3 = bc & 3;
        float4 r;
        r.x = mid[(4 * j + 0) * BC_ + 4 * (c4 ^ j) + b3];
        r.y = mid[(4 * j + 1) * BC_ + 4 * (c4 ^ j) + b3];
        r.z = mid[(4 * j + 2) * BC_ + 4 * (c4 ^ j) + b3];
        r.w = mid[(4 * j + 3) * BC_ + 4 * (c4 ^ j) + b3];
        float4* __restrict__ dst =
            reinterpret_cast<float4*>(out + (size_t)bc * M_);
        __stcs(&dst[N4_ + (e0 >> 2) + j], r);
    }
}

extern "C" void kernel_launch(void* const* d_in, const int* in_sizes, int n_in,
                              void* d_out, int out_size) {
    const float* data  = (const float*)d_in[0];
    const int*   edges = (const int*)d_in[1];
    float*       out   = (float*)d_out;

    transpose_kernel<<<dim3(N_ / 32, BC_ / 128), 256>>>(data);
    gather_mid_kernel<<<E_ / TILE_E, 512>>>(edges, out);
}